// round 16
// baseline (speedup 1.0000x reference)
#include <cuda_runtime.h>
#include <cuda_bf16.h>

// ---------------- problem constants ----------------
#define MAXN 100000
#define MAXE 1600000
#define SCAN_B 1024

// ---------------- scratch (device globals; no allocations allowed) ----------
__device__ __align__(16) float g_h   [MAXN * 64];   // transformed features (X@W)
__device__ __align__(16) float g_act [MAXN * 64];   // layer activations
__device__ float g_dinv  [MAXN];
__device__ int   g_cnt   [MAXN];
__device__ int   g_tmp   [MAXN];                    // per-block inclusive scan
__device__ int   g_bsum  [256];                     // block sums
__device__ int   g_rowptr[MAXN + 1];
__device__ __align__(16) int2 g_epack[MAXE];        // CSR-by-dst: (src, norm-bits)

// ---------------- packed fp32x2 FMA (Blackwell FFMA2) ----------------
__device__ __forceinline__ unsigned long long fma_f32x2(
    unsigned long long a, unsigned long long b, unsigned long long c) {
    unsigned long long d;
    asm("fma.rn.f32x2 %0, %1, %2, %3;" : "=l"(d) : "l"(a), "l"(b), "l"(c));
    return d;
}
__device__ __forceinline__ float pair_sum(unsigned long long v) {
    float lo, hi;
    asm("mov.b64 {%0, %1}, %2;" : "=f"(lo), "=f"(hi) : "l"(v));
    return lo + hi;
}

// ---------------- CSR build ----------------
__global__ void init_cnt_kernel(int* __restrict__ cnt, int n) {
    int i = blockIdx.x * blockDim.x + threadIdx.x;
    if (i < n) cnt[i] = 0;
}

// edge_index int32: ei[0:E]=src, ei[E:2E]=dst
__global__ void count_kernel(const int* __restrict__ ei, int* __restrict__ cnt,
                             int E, int n) {
    int e = blockIdx.x * blockDim.x + threadIdx.x;
    if (e >= E) return;
    int d = ei[E + e];
    if ((unsigned)d < (unsigned)n) atomicAdd(&cnt[d], 1);
}

// inclusive scan within blocks of SCAN_B
__global__ void scan_block_kernel(const int* __restrict__ cnt, int* __restrict__ tmp,
                                  int* __restrict__ bsum, int n) {
    __shared__ int sh[SCAN_B];
    int i = blockIdx.x * SCAN_B + threadIdx.x;
    int v = (i < n) ? cnt[i] : 0;
    sh[threadIdx.x] = v;
    __syncthreads();
    for (int off = 1; off < SCAN_B; off <<= 1) {
        int t = (threadIdx.x >= off) ? sh[threadIdx.x - off] : 0;
        __syncthreads();
        sh[threadIdx.x] += t;
        __syncthreads();
    }
    if (i < n) tmp[i] = sh[threadIdx.x];
    if (threadIdx.x == SCAN_B - 1) bsum[blockIdx.x] = sh[SCAN_B - 1];
}

// exclusive scan of block sums (single block, nb <= 256)
__global__ void scan_bsum_kernel(int* __restrict__ bsum, int nb) {
    __shared__ int sh[256];
    int t = threadIdx.x;
    int v = (t < nb) ? bsum[t] : 0;
    sh[t] = v;
    __syncthreads();
    for (int off = 1; off < 256; off <<= 1) {
        int u = (t >= off) ? sh[t - off] : 0;
        __syncthreads();
        sh[t] += u;
        __syncthreads();
    }
    if (t < nb) bsum[t] = sh[t] - v;   // exclusive
}

// rowptr + dinv + cursor reset, fused
__global__ void rowptr_kernel(const int* __restrict__ tmp, const int* __restrict__ bsum,
                              int* __restrict__ rowptr, int* __restrict__ cnt,
                              float* __restrict__ dinv, int n) {
    int i = blockIdx.x * blockDim.x + threadIdx.x;
    if (i < n) {
        rowptr[i + 1] = tmp[i] + bsum[i / SCAN_B];
        dinv[i] = rsqrtf((float)cnt[i] + 1.0f);   // +1 self-loop
        cnt[i] = 0;                               // reuse as fill cursor
    }
    if (i == 0) rowptr[0] = 0;
}

__global__ void fill_csr_kernel(const int* __restrict__ ei, const float* __restrict__ dinv,
                                const int* __restrict__ rowptr, int* __restrict__ cnt,
                                int2* __restrict__ epack, int E, int n) {
    int e = blockIdx.x * blockDim.x + threadIdx.x;
    if (e >= E) return;
    int s = ei[e];
    int d = ei[E + e];
    if ((unsigned)s >= (unsigned)n || (unsigned)d >= (unsigned)n) return;
    int pos = rowptr[d] + atomicAdd(&cnt[d], 1);
    epack[pos] = make_int2(s, __float_as_int(dinv[s] * dinv[d]));
}

// ---------------- dense GEMM: H = X @ W (in_f=64) ----------------
// FFMA2 version: even/odd k accumulate in the two f32x2 lanes.
// W staged transposed as k-pair u64s; per 2-k step: 4 LDS.64 + 2 LDS.128 + 16 FFMA2.
template<int OUTF>
__global__ void gemm_kernel(const float* __restrict__ X, const float* __restrict__ W,
                            float* __restrict__ H, int n) {
    constexpr int TPR = OUTF / 4;                 // threads per row-group (4 cols each)
    constexpr int RPB = (256 / TPR) * 4;          // rows per block (4 rows/thread)
    __shared__ unsigned long long sWT[32 * OUTF]; // [p][c] = (W[2p][c], W[2p+1][c])
    __shared__ float sX[RPB * 64];
    for (int i = threadIdx.x; i < 32 * OUTF; i += 256) {
        int p = i / OUTF, c = i % OUTF;
        float w0 = W[(2 * p) * OUTF + c];
        float w1 = W[(2 * p + 1) * OUTF + c];
        unsigned long long pk;
        asm("mov.b64 %0, {%1, %2};" : "=l"(pk) : "f"(w0), "f"(w1));
        sWT[i] = pk;
    }
    int row0 = blockIdx.x * RPB;
    for (int i = threadIdx.x; i < RPB * 16; i += 256) {   // float4 fills
        int r = row0 + (i >> 4);
        ((float4*)sX)[i] = (r < n) ? ((const float4*)(X + (size_t)r * 64))[i & 15]
                                   : make_float4(0.f, 0.f, 0.f, 0.f);
    }
    __syncthreads();
    int lr = (threadIdx.x / TPR) * 4;             // first of 4 local rows
    int c0 = (threadIdx.x % TPR) * 4;             // first of 4 cols
    unsigned long long acc[4][4];
    #pragma unroll
    for (int r = 0; r < 4; r++)
        #pragma unroll
        for (int c = 0; c < 4; c++) acc[r][c] = 0ull;   // (0.f,0.f)

    #pragma unroll
    for (int p = 0; p < 32; p++) {
        ulonglong2 wA = *(const ulonglong2*)&sWT[p * OUTF + c0];
        ulonglong2 wB = *(const ulonglong2*)&sWT[p * OUTF + c0 + 2];
        #pragma unroll
        for (int r = 0; r < 4; r++) {
            unsigned long long xp =
                *(const unsigned long long*)&sX[(lr + r) * 64 + 2 * p];
            acc[r][0] = fma_f32x2(xp, wA.x, acc[r][0]);
            acc[r][1] = fma_f32x2(xp, wA.y, acc[r][1]);
            acc[r][2] = fma_f32x2(xp, wB.x, acc[r][2]);
            acc[r][3] = fma_f32x2(xp, wB.y, acc[r][3]);
        }
    }
    int row = row0 + lr;
    #pragma unroll
    for (int r = 0; r < 4; r++) {
        if (row + r < n) {
            float4 o = make_float4(pair_sum(acc[r][0]), pair_sum(acc[r][1]),
                                   pair_sum(acc[r][2]), pair_sum(acc[r][3]));
            *(float4*)(H + (size_t)(row + r) * OUTF + c0) = o;
        }
    }
}

// ---------------- fused gather-aggregate + finalize (64-wide) ----------------
template<bool RELU>
__global__ void gather64_kernel(const int* __restrict__ rowptr,
                                const int2* __restrict__ epack,
                                const float* __restrict__ H, const float* __restrict__ dinv,
                                const float* __restrict__ bias,
                                float* __restrict__ OUT, int n) {
    int warp = (blockIdx.x * blockDim.x + threadIdx.x) >> 5;
    int lane = threadIdx.x & 31;
    if (warp >= n) return;
    int node = warp;
    int half = lane >> 4;
    int col  = (lane & 15) * 4;
    int beg = __ldg(&rowptr[node]);
    int end = __ldg(&rowptr[node + 1]);

    float4 acc = make_float4(0.f, 0.f, 0.f, 0.f);
    int i = beg + half;
    for (; i + 6 < end; i += 8) {
        int2 e0 = __ldg(&epack[i]);
        int2 e1 = __ldg(&epack[i + 2]);
        int2 e2 = __ldg(&epack[i + 4]);
        int2 e3 = __ldg(&epack[i + 6]);
        float4 v0 = *(const float4*)(H + (size_t)e0.x * 64 + col);
        float4 v1 = *(const float4*)(H + (size_t)e1.x * 64 + col);
        float4 v2 = *(const float4*)(H + (size_t)e2.x * 64 + col);
        float4 v3 = *(const float4*)(H + (size_t)e3.x * 64 + col);
        float w0 = __int_as_float(e0.y), w1 = __int_as_float(e1.y);
        float w2 = __int_as_float(e2.y), w3 = __int_as_float(e3.y);
        acc.x += w0 * v0.x + w1 * v1.x + w2 * v2.x + w3 * v3.x;
        acc.y += w0 * v0.y + w1 * v1.y + w2 * v2.y + w3 * v3.y;
        acc.z += w0 * v0.z + w1 * v1.z + w2 * v2.z + w3 * v3.z;
        acc.w += w0 * v0.w + w1 * v1.w + w2 * v2.w + w3 * v3.w;
    }
    for (; i < end; i += 2) {
        int2 e0 = __ldg(&epack[i]);
        float4 v0 = *(const float4*)(H + (size_t)e0.x * 64 + col);
        float w0 = __int_as_float(e0.y);
        acc.x += w0 * v0.x; acc.y += w0 * v0.y;
        acc.z += w0 * v0.z; acc.w += w0 * v0.w;
    }
    acc.x += __shfl_xor_sync(0xffffffffu, acc.x, 16);
    acc.y += __shfl_xor_sync(0xffffffffu, acc.y, 16);
    acc.z += __shfl_xor_sync(0xffffffffu, acc.z, 16);
    acc.w += __shfl_xor_sync(0xffffffffu, acc.w, 16);

    if (half == 0) {
        float di = __ldg(&dinv[node]);
        float sl = di * di;
        float4 hh = *(const float4*)(H + (size_t)node * 64 + col);
        float4 bb = *(const float4*)(bias + col);
        float4 o;
        o.x = acc.x + sl * hh.x + bb.x;
        o.y = acc.y + sl * hh.y + bb.y;
        o.z = acc.z + sl * hh.z + bb.z;
        o.w = acc.w + sl * hh.w + bb.w;
        if (RELU) {
            o.x = fmaxf(o.x, 0.f); o.y = fmaxf(o.y, 0.f);
            o.z = fmaxf(o.z, 0.f); o.w = fmaxf(o.w, 0.f);
        }
        *(float4*)(OUT + (size_t)node * 64 + col) = o;
    }
}

// ---------------- fused gather-aggregate + finalize (32-wide) ----------------
template<bool RELU>
__global__ void gather32_kernel(const int* __restrict__ rowptr,
                                const int2* __restrict__ epack,
                                const float* __restrict__ H, const float* __restrict__ dinv,
                                const float* __restrict__ bias,
                                float* __restrict__ OUT, int n) {
    int warp = (blockIdx.x * blockDim.x + threadIdx.x) >> 5;
    int lane = threadIdx.x & 31;
    if (warp >= n) return;
    int node = warp;
    int grp = lane >> 3;
    int col = (lane & 7) * 4;
    int beg = __ldg(&rowptr[node]);
    int end = __ldg(&rowptr[node + 1]);

    float4 acc = make_float4(0.f, 0.f, 0.f, 0.f);
    int i = beg + grp;
    for (; i + 12 < end; i += 16) {
        int2 e0 = __ldg(&epack[i]);
        int2 e1 = __ldg(&epack[i + 4]);
        int2 e2 = __ldg(&epack[i + 8]);
        int2 e3 = __ldg(&epack[i + 12]);
        float4 v0 = *(const float4*)(H + (size_t)e0.x * 32 + col);
        float4 v1 = *(const float4*)(H + (size_t)e1.x * 32 + col);
        float4 v2 = *(const float4*)(H + (size_t)e2.x * 32 + col);
        float4 v3 = *(const float4*)(H + (size_t)e3.x * 32 + col);
        float w0 = __int_as_float(e0.y), w1 = __int_as_float(e1.y);
        float w2 = __int_as_float(e2.y), w3 = __int_as_float(e3.y);
        acc.x += w0 * v0.x + w1 * v1.x + w2 * v2.x + w3 * v3.x;
        acc.y += w0 * v0.y + w1 * v1.y + w2 * v2.y + w3 * v3.y;
        acc.z += w0 * v0.z + w1 * v1.z + w2 * v2.z + w3 * v3.z;
        acc.w += w0 * v0.w + w1 * v1.w + w2 * v2.w + w3 * v3.w;
    }
    for (; i < end; i += 4) {
        int2 e0 = __ldg(&epack[i]);
        float4 v0 = *(const float4*)(H + (size_t)e0.x * 32 + col);
        float w0 = __int_as_float(e0.y);
        acc.x += w0 * v0.x; acc.y += w0 * v0.y;
        acc.z += w0 * v0.z; acc.w += w0 * v0.w;
    }
    #pragma unroll
    for (int off = 8; off <= 16; off <<= 1) {
        acc.x += __shfl_xor_sync(0xffffffffu, acc.x, off);
        acc.y += __shfl_xor_sync(0xffffffffu, acc.y, off);
        acc.z += __shfl_xor_sync(0xffffffffu, acc.z, off);
        acc.w += __shfl_xor_sync(0xffffffffu, acc.w, off);
    }
    if (lane < 8) {
        float di = __ldg(&dinv[node]);
        float sl = di * di;
        float4 hh = *(const float4*)(H + (size_t)node * 32 + col);
        float4 bb = *(const float4*)(bias + col);
        float4 o;
        o.x = acc.x + sl * hh.x + bb.x;
        o.y = acc.y + sl * hh.y + bb.y;
        o.z = acc.z + sl * hh.z + bb.z;
        o.w = acc.w + sl * hh.w + bb.w;
        if (RELU) {
            o.x = fmaxf(o.x, 0.f); o.y = fmaxf(o.y, 0.f);
            o.z = fmaxf(o.z, 0.f); o.w = fmaxf(o.w, 0.f);
        }
        *(float4*)(OUT + (size_t)node * 32 + col) = o;
    }
}

// ---------------- launch ----------------
extern "C" void kernel_launch(void* const* d_in, const int* in_sizes, int n_in,
                              void* d_out, int out_size) {
    const float* x  = (const float*)d_in[0];
    const int*   ei = (const int*)d_in[1];      // int32: [0:E]=src, [E:2E]=dst
    const float* W1 = (const float*)d_in[2];
    const float* b1 = (const float*)d_in[3];
    const float* W2 = (const float*)d_in[4];
    const float* b2 = (const float*)d_in[5];
    const float* W3 = (const float*)d_in[6];
    const float* b3 = (const float*)d_in[7];
    float* out = (float*)d_out;

    const int n = in_sizes[0] / 64;
    const int E = in_sizes[1] / 2;

    float *p_h, *p_act, *p_dinv;
    int *p_cnt, *p_tmp, *p_bsum, *p_rowptr;
    int2 *p_epack;
    cudaGetSymbolAddress((void**)&p_h,      g_h);
    cudaGetSymbolAddress((void**)&p_act,    g_act);
    cudaGetSymbolAddress((void**)&p_dinv,   g_dinv);
    cudaGetSymbolAddress((void**)&p_cnt,    g_cnt);
    cudaGetSymbolAddress((void**)&p_tmp,    g_tmp);
    cudaGetSymbolAddress((void**)&p_bsum,   g_bsum);
    cudaGetSymbolAddress((void**)&p_rowptr, g_rowptr);
    cudaGetSymbolAddress((void**)&p_epack,  g_epack);

    const int B = 256;
    int gb_n  = (n + B - 1) / B;
    int gb_e  = (E + B - 1) / B;
    int nb    = (n + SCAN_B - 1) / SCAN_B;

    // ---- CSR build (amortized over 3 layers) ----
    init_cnt_kernel<<<gb_n, B>>>(p_cnt, n);
    count_kernel<<<gb_e, B>>>(ei, p_cnt, E, n);
    scan_block_kernel<<<nb, SCAN_B>>>(p_cnt, p_tmp, p_bsum, n);
    scan_bsum_kernel<<<1, 256>>>(p_bsum, nb);
    rowptr_kernel<<<gb_n, B>>>(p_tmp, p_bsum, p_rowptr, p_cnt, p_dinv, n);
    fill_csr_kernel<<<gb_e, B>>>(ei, p_dinv, p_rowptr, p_cnt, p_epack, E, n);

    int gb_gemm64 = (n + 63) / 64;             // 64 rows/block
    int gb_gemm32 = (n + 127) / 128;           // 128 rows/block
    int gb_gather = (n * 32 + B - 1) / B;      // 1 warp per node

    // ---- layer 1: x -> g_act ----
    gemm_kernel<64><<<gb_gemm64, B>>>(x, W1, p_h, n);
    gather64_kernel<true><<<gb_gather, B>>>(p_rowptr, p_epack, p_h, p_dinv, b1, p_act, n);

    // ---- layer 2: g_act -> g_act ----
    gemm_kernel<64><<<gb_gemm64, B>>>(p_act, W2, p_h, n);
    gather64_kernel<true><<<gb_gather, B>>>(p_rowptr, p_epack, p_h, p_dinv, b2, p_act, n);

    // ---- layer 3: g_act -> out (no relu) ----
    gemm_kernel<32><<<gb_gemm32, B>>>(p_act, W3, p_h, n);
    gather32_kernel<false><<<gb_gather, B>>>(p_rowptr, p_epack, p_h, p_dinv, b3, out, n);
}